// round 4
// baseline (speedup 1.0000x reference)
#include <cuda_runtime.h>
#include <cstdint>

#define NF   2
#define NLOC 4096
#define NNEI 64
#define NALL 6144
#define NG1  128
#define NG2  32
#define NDD  32
#define NH   4

// Precomputed folded weight matrices (scratch; __device__ globals are allowed)
__device__ __align__(16) float g_M[4 * 32 * 32];  // [h][a][b] = Wq_h Wk_h^T / sqrt(nd)
__device__ __align__(16) float g_P[4 * 32 * 32];  // [h][a][j] = Wv_h @ Whm_h

__global__ void prep_kernel(const float* __restrict__ wqk,
                            const float* __restrict__ wv,
                            const float* __restrict__ whm) {
    int t = threadIdx.x;  // 256 threads
    const float inv_sqrt_nd = 0.17677669529663689f;  // 1/sqrt(32)
    for (int i = 0; i < 16; ++i) {
        int idx = t + 256 * i;                 // [h][a][b]
        int h = idx >> 10, a = (idx >> 5) & 31, b = idx & 31;
        float s = 0.f;
        for (int d = 0; d < 32; ++d)
            s += wqk[a * 256 + d * 8 + h] * wqk[b * 256 + d * 8 + 4 + h];
        g_M[idx] = s * inv_sqrt_nd;
    }
    for (int i = 0; i < 16; ++i) {
        int idx = t + 256 * i;                 // [h][a][j]
        int h = idx >> 10, a = (idx >> 5) & 31, j = idx & 31;
        float s = 0.f;
        for (int c = 0; c < 32; ++c)
            s += wv[a * 128 + c * 4 + h] * whm[(c * 4 + h) * 32 + j];
        g_P[idx] = s;
    }
}

// Dynamic smem layout (float offsets)
#define OFF_G2U  0              // [64][32]  unpadded (uniform/float4 reads)
#define OFF_G2P  2048           // [64][33]  padded (lane-varying reads)
#define OFF_U    4160           // [4][64][36] (stride 36 keeps 16B alignment)
#define OFF_AA   13376          // [4][64][65]
#define OFF_H2   30016          // [64][4]
#define OFF_SW   30272          // [64]
#define OFF_MK   30336          // [64]
#define OFF_BIAS 30400          // [32]
#define OFF_WEV  30432          // [4]
#define OFF_NLS  30436          // [64] ints
#define SMEM_FLOATS 30512

extern __shared__ float sm[];

__global__ void __launch_bounds__(256, 1)
repformer_kernel(const float* __restrict__ g1_ext,
                 const float* __restrict__ g2,
                 const float* __restrict__ h2,
                 const float* __restrict__ sw,
                 const float* __restrict__ bhm,
                 const float* __restrict__ wev_g,
                 const int* __restrict__ nlist,
                 const int* __restrict__ nmask,
                 float* __restrict__ out_gg1,
                 float* __restrict__ out_g2,
                 float* __restrict__ out_h2) {
    float* g2u  = sm + OFF_G2U;
    float* g2p  = sm + OFF_G2P;
    float* Us   = sm + OFF_U;
    float* AAs  = sm + OFF_AA;
    float* h2s  = sm + OFF_H2;
    float* sws  = sm + OFF_SW;
    float* msk  = sm + OFF_MK;
    float* bias = sm + OFF_BIAS;
    float* wev  = sm + OFF_WEV;
    int*   nls  = (int*)(sm + OFF_NLS);

    const int t = threadIdx.x;
    const int tile = blockIdx.x;            // b*NLOC + l
    const int b = tile >> 12;               // NLOC = 4096

    // ---------------- Phase 1: load tile inputs into smem ----------------
    {
        const float4* g2g = (const float4*)(g2 + (size_t)tile * (NNEI * NG2));
        #pragma unroll
        for (int i = 0; i < 2; ++i) {
            int v = t + 256 * i;            // 512 float4 total
            float4 x = __ldg(&g2g[v]);
            ((float4*)g2u)[v] = x;
            int n = v >> 3, c = (v & 7) * 4;
            float* r = &g2p[n * 33 + c];
            r[0] = x.x; r[1] = x.y; r[2] = x.z; r[3] = x.w;
        }
        if (t < 192) h2s[(t / 3) * 4 + (t % 3)] = __ldg(&h2[(size_t)tile * 192 + t]);
        if (t < 64) {
            sws[t] = __ldg(&sw[(size_t)tile * 64 + t]);
            msk[t] = (__ldg(&nmask[(size_t)tile * 64 + t]) != 0) ? 1.f : 0.f;
            nls[t] = __ldg(&nlist[(size_t)tile * 64 + t]);
        }
        if (t < 32) bias[t] = __ldg(&bhm[t]);
        if (t < 4)  wev[t]  = __ldg(&wev_g[t]);
    }
    __syncthreads();

    // ---------------- gg1 gather (overlaps with compute below) ----------------
    {
        float4* dst = (float4*)(out_gg1 + (size_t)tile * (NNEI * NG1));
        const float4* src = (const float4*)(g1_ext + (size_t)b * NALL * NG1);
        #pragma unroll
        for (int i = 0; i < 8; ++i) {
            int v = t + 256 * i;            // 2048 float4
            int nn = v >> 5, c4 = v & 31;   // nn warp-uniform
            float4 o;
            if (msk[nn] != 0.f) {
                float sv = sws[nn];
                float4 x = __ldg(&src[(size_t)nls[nn] * 32 + c4]);
                o = make_float4(x.x * sv, x.y * sv, x.z * sv, x.w * sv);
            } else {
                o = make_float4(0.f, 0.f, 0.f, 0.f);
            }
            dst[v] = o;
        }
    }

    const int h = t >> 6;   // warp-uniform head
    const int n = t & 63;   // neighbor index (query / row role)

    // ---------------- Phase 2: Tr[b] = sum_a g2[n,a] * M_h[a,b] (kept in regs) ----------------
    float Tr[32];
    #pragma unroll
    for (int i = 0; i < 32; ++i) Tr[i] = 0.f;
    {
        const float4* M4 = (const float4*)g_M;
        for (int c = 0; c < 32; ++c) {
            float g = g2p[n * 33 + c];
            const float4* mp = &M4[(h * 32 + c) * 8];
            #pragma unroll
            for (int b4 = 0; b4 < 8; ++b4) {
                float4 mm = __ldg(&mp[b4]);
                Tr[b4 * 4 + 0] += g * mm.x;
                Tr[b4 * 4 + 1] += g * mm.y;
                Tr[b4 * 4 + 2] += g * mm.z;
                Tr[b4 * 4 + 3] += g * mm.w;
            }
        }
    }

    // ---------------- Phase 3: U[h][n][j] = g2[n,:] @ P_h ----------------
    {
        float Ua[32];
        #pragma unroll
        for (int i = 0; i < 32; ++i) Ua[i] = 0.f;
        const float4* P4 = (const float4*)g_P;
        for (int c = 0; c < 32; ++c) {
            float g = g2p[n * 33 + c];
            const float4* pp = &P4[(h * 32 + c) * 8];
            #pragma unroll
            for (int j4 = 0; j4 < 8; ++j4) {
                float4 pv = __ldg(&pp[j4]);
                Ua[j4 * 4 + 0] += g * pv.x;
                Ua[j4 * 4 + 1] += g * pv.y;
                Ua[j4 * 4 + 2] += g * pv.z;
                Ua[j4 * 4 + 3] += g * pv.w;
            }
        }
        float* urow = &Us[(h * 64 + n) * 36];
        #pragma unroll
        for (int j4 = 0; j4 < 8; ++j4)
            *(float4*)(urow + j4 * 4) =
                make_float4(Ua[j4 * 4 + 0], Ua[j4 * 4 + 1], Ua[j4 * 4 + 2], Ua[j4 * 4 + 3]);
    }

    // ---------------- Phase 4: attention row (score, softmax, mask, -> AA) ----------------
    {
        float* arow = &AAs[(h * 64 + n) * 65];
        const float h20 = h2s[n * 4 + 0], h21 = h2s[n * 4 + 1], h22 = h2s[n * 4 + 2];
        const float swn = sws[n], mkn = msk[n];
        float maxv = -1e30f;
        for (int m = 0; m < 64; ++m) {
            float acc = 0.f;
            const float4* gr = (const float4*)&g2u[m * 32];
            #pragma unroll
            for (int a4 = 0; a4 < 8; ++a4) {
                float4 g = gr[a4];
                acc += Tr[a4 * 4 + 0] * g.x + Tr[a4 * 4 + 1] * g.y +
                       Tr[a4 * 4 + 2] * g.z + Tr[a4 * 4 + 3] * g.w;
            }
            float gate = h20 * h2s[m * 4 + 0] + h21 * h2s[m * 4 + 1] + h22 * h2s[m * 4 + 2];
            float sw2 = swn * sws[m];
            float s = (acc * gate + 20.f) * sw2 - 20.f;
            arow[m] = s;
            maxv = fmaxf(maxv, s);
        }
        float sum = 0.f;
        for (int m = 0; m < 64; ++m) {
            float e = __expf(arow[m] - maxv);
            arow[m] = e;
            sum += e;
        }
        // fold mask_n and 1/sqrt(3) (h2h2t scale) into normalizer
        float inv = mkn * 0.5773502691896258f / sum;
        for (int m = 0; m < 64; ++m) {
            float gate = h20 * h2s[m * 4 + 0] + h21 * h2s[m * 4 + 1] + h22 * h2s[m * 4 + 2];
            float sw2 = swn * sws[m];
            arow[m] = arow[m] * inv * msk[m] * sw2 * gate;  // AA[n,m,h]
        }
    }
    __syncthreads();

    // ---------------- Phase 6: g2_out[n,j] = sum_{m,h} AA*U + bias ; h2_out ----------------
    {
        const int n2 = t >> 2;      // 64 rows
        const int jg = t & 3;       // 4 column groups of 8
        float cacc[8];
        #pragma unroll
        for (int i = 0; i < 8; ++i) cacc[i] = 0.f;
        float hx0 = 0.f, hx1 = 0.f, hx2 = 0.f;
        const float w0 = wev[0], w1 = wev[1], w2 = wev[2], w3 = wev[3];
        const int mlo = jg * 16, mhi = mlo + 16;

        for (int m = 0; m < 64; ++m) {
            float a0 = AAs[(0 * 64 + n2) * 65 + m];
            float a1 = AAs[(1 * 64 + n2) * 65 + m];
            float a2 = AAs[(2 * 64 + n2) * 65 + m];
            float a3 = AAs[(3 * 64 + n2) * 65 + m];

            #pragma unroll
            for (int jj4 = 0; jj4 < 2; ++jj4) {
                float4 u0 = *(const float4*)&Us[(0 * 64 + m) * 36 + jg * 8 + jj4 * 4];
                float4 u1 = *(const float4*)&Us[(1 * 64 + m) * 36 + jg * 8 + jj4 * 4];
                float4 u2 = *(const float4*)&Us[(2 * 64 + m) * 36 + jg * 8 + jj4 * 4];
                float4 u3 = *(const float4*)&Us[(3 * 64 + m) * 36 + jg * 8 + jj4 * 4];
                cacc[jj4 * 4 + 0] += a0 * u0.x + a1 * u1.x + a2 * u2.x + a3 * u3.x;
                cacc[jj4 * 4 + 1] += a0 * u0.y + a1 * u1.y + a2 * u2.y + a3 * u3.y;
                cacc[jj4 * 4 + 2] += a0 * u0.z + a1 * u1.z + a2 * u2.z + a3 * u3.z;
                cacc[jj4 * 4 + 3] += a0 * u0.w + a1 * u1.w + a2 * u2.w + a3 * u3.w;
            }
            if (m >= mlo && m < mhi) {   // partition m over the quad for h2_out
                float aw = a0 * w0 + a1 * w1 + a2 * w2 + a3 * w3;
                hx0 += aw * h2s[m * 4 + 0];
                hx1 += aw * h2s[m * 4 + 1];
                hx2 += aw * h2s[m * 4 + 2];
            }
        }
        // quad reduce h2_out partials
        hx0 += __shfl_xor_sync(0xffffffffu, hx0, 1);
        hx0 += __shfl_xor_sync(0xffffffffu, hx0, 2);
        hx1 += __shfl_xor_sync(0xffffffffu, hx1, 1);
        hx1 += __shfl_xor_sync(0xffffffffu, hx1, 2);
        hx2 += __shfl_xor_sync(0xffffffffu, hx2, 1);
        hx2 += __shfl_xor_sync(0xffffffffu, hx2, 2);
        if (jg == 0) {
            float* ho = out_h2 + (size_t)tile * 192 + n2 * 3;
            ho[0] = hx0; ho[1] = hx1; ho[2] = hx2;
        }
        #pragma unroll
        for (int jj = 0; jj < 8; ++jj) cacc[jj] += bias[jg * 8 + jj];
        float* go = out_g2 + ((size_t)tile * 64 + n2) * 32 + jg * 8;
        *(float4*)(go + 0) = make_float4(cacc[0], cacc[1], cacc[2], cacc[3]);
        *(float4*)(go + 4) = make_float4(cacc[4], cacc[5], cacc[6], cacc[7]);
    }
}

extern "C" void kernel_launch(void* const* d_in, const int* in_sizes, int n_in,
                              void* d_out, int out_size) {
    (void)in_sizes; (void)n_in; (void)out_size;
    const float* g1_ext = (const float*)d_in[0];
    const float* g2     = (const float*)d_in[1];
    const float* h2     = (const float*)d_in[2];
    const float* sw     = (const float*)d_in[3];
    const float* wqk    = (const float*)d_in[4];
    const float* wv     = (const float*)d_in[5];
    const float* whm    = (const float*)d_in[6];
    const float* bhm    = (const float*)d_in[7];
    const float* wev    = (const float*)d_in[8];
    const int* nlist    = (const int*)d_in[9];
    const int* nmask    = (const int*)d_in[10];

    float* out = (float*)d_out;
    float* out_gg1 = out;                                 // 2*4096*64*128
    float* out_g2  = out + 67108864ll;                    // 2*4096*64*32
    float* out_h2  = out + 83886080ll;                    // 2*4096*64*3

    size_t smem = SMEM_FLOATS * sizeof(float);            // ~122 KB
    cudaFuncSetAttribute(repformer_kernel,
                         cudaFuncAttributeMaxDynamicSharedMemorySize, (int)smem);

    prep_kernel<<<1, 256>>>(wqk, wv, whm);
    repformer_kernel<<<NF * NLOC, 256, smem>>>(
        g1_ext, g2, h2, sw, bhm, wev, nlist, nmask,
        out_gg1, out_g2, out_h2);
}

// round 5
// speedup vs baseline: 1.4415x; 1.4415x over previous
#include <cuda_runtime.h>
#include <cstdint>

#define NF   2
#define NLOC 4096
#define NNEI 64
#define NALL 6144
#define NG1  128
#define NG2  32
#define NH   4

// Folded weights: M_h = Wq_h Wk_h^T / sqrt(32), P_h = Wv_h @ Whm_h
__device__ __align__(16) float g_M[4 * 32 * 32];
__device__ __align__(16) float g_P[4 * 32 * 32];

__global__ void prep_kernel(const float* __restrict__ wqk,
                            const float* __restrict__ wv,
                            const float* __restrict__ whm) {
    int t = threadIdx.x;  // 256 threads
    const float inv_sqrt_nd = 0.17677669529663689f;
    for (int i = 0; i < 16; ++i) {
        int idx = t + 256 * i;                 // [h][a][b]
        int h = idx >> 10, a = (idx >> 5) & 31, b = idx & 31;
        float s = 0.f;
        for (int d = 0; d < 32; ++d)
            s += wqk[a * 256 + d * 8 + h] * wqk[b * 256 + d * 8 + 4 + h];
        g_M[idx] = s * inv_sqrt_nd;
    }
    for (int i = 0; i < 16; ++i) {
        int idx = t + 256 * i;                 // [h][a][j]
        int h = idx >> 10, a = (idx >> 5) & 31, j = idx & 31;
        float s = 0.f;
        for (int c = 0; c < 32; ++c)
            s += wv[a * 128 + c * 4 + h] * whm[(c * 4 + h) * 32 + j];
        g_P[idx] = s;
    }
}

// packed f32x2 helpers
static __device__ __forceinline__ unsigned long long ffma2(
    unsigned long long a, unsigned long long b, unsigned long long c) {
    unsigned long long d;
    asm("fma.rn.f32x2 %0, %1, %2, %3;" : "=l"(d) : "l"(a), "l"(b), "l"(c));
    return d;
}
static __device__ __forceinline__ unsigned long long pack2(float lo, float hi) {
    unsigned long long d;
    asm("mov.b64 %0, {%1, %2};" : "=l"(d) : "f"(lo), "f"(hi));
    return d;
}
static __device__ __forceinline__ float2 unpack2(unsigned long long v) {
    float lo, hi;
    asm("mov.b64 {%0, %1}, %2;" : "=f"(lo), "=f"(hi) : "l"(v));
    return make_float2(lo, hi);
}

// Smem layout (float offsets)
#define OFF_G2   0                       // [64][36]
#define OFF_U    2304                    // [4][64][36]
#define OFF_AA   11520                   // [4][64][65]
#define OFF_H2   28160                   // [64][4]
#define OFF_SW   28416                   // [64]
#define OFF_MK   28480                   // [64]
#define OFF_BIAS 28544                   // [32]
#define OFF_WEV  28576                   // [4]
#define OFF_NLS  28580                   // [64] ints
#define SMEM_FLOATS 28644                // 114576 B

extern __shared__ float sm[];

__global__ void __launch_bounds__(256, 2)
repformer_kernel(const float* __restrict__ g1_ext,
                 const float* __restrict__ g2,
                 const float* __restrict__ h2,
                 const float* __restrict__ sw,
                 const float* __restrict__ bhm,
                 const float* __restrict__ wev_g,
                 const int* __restrict__ nlist,
                 const int* __restrict__ nmask,
                 float* __restrict__ out_gg1,
                 float* __restrict__ out_g2,
                 float* __restrict__ out_h2) {
    float* g2s  = sm + OFF_G2;
    float* Us   = sm + OFF_U;
    float* AAs  = sm + OFF_AA;
    float* h2s  = sm + OFF_H2;
    float* sws  = sm + OFF_SW;
    float* msk  = sm + OFF_MK;
    float* bias = sm + OFF_BIAS;
    float* wev  = sm + OFF_WEV;
    int*   nls  = (int*)(sm + OFF_NLS);

    const int t = threadIdx.x;
    const int tile = blockIdx.x;
    const int b = tile >> 12;

    // ---------------- Phase 1: stage tile inputs ----------------
    {
        const float4* g2g = (const float4*)(g2 + (size_t)tile * (NNEI * NG2));
        #pragma unroll
        for (int i = 0; i < 2; ++i) {
            int v = t + 256 * i;             // 512 float4
            float4 x = __ldg(&g2g[v]);
            int row = v >> 3, c4 = (v & 7) * 4;
            *(float4*)(g2s + row * 36 + c4) = x;
        }
        if (t < 192) h2s[(t / 3) * 4 + (t % 3)] = __ldg(&h2[(size_t)tile * 192 + t]);
        if (t < 64) {
            h2s[t * 4 + 3] = 0.f;
            sws[t] = __ldg(&sw[(size_t)tile * 64 + t]);
            msk[t] = (__ldg(&nmask[(size_t)tile * 64 + t]) != 0) ? 1.f : 0.f;
            nls[t] = __ldg(&nlist[(size_t)tile * 64 + t]);
        }
        if (t < 32) bias[t] = __ldg(&bhm[t]);
        if (t < 4)  wev[t]  = __ldg(&wev_g[t]);
    }
    __syncthreads();

    if (t >= 128) {
        // ============ GATHER WARPS (4 warps): gg1 ============
        const int tg = t - 128;
        float4* dst = (float4*)(out_gg1 + (size_t)tile * (NNEI * NG1));
        const float4* src = (const float4*)(g1_ext + (size_t)b * NALL * NG1);
        #pragma unroll 4
        for (int i = 0; i < 16; ++i) {
            int v = tg + 128 * i;            // 2048 float4
            int nn = v >> 5, c4 = v & 31;
            float4 o;
            if (msk[nn] != 0.f) {
                float sv = sws[nn];
                float4 x = __ldg(&src[(size_t)nls[nn] * 32 + c4]);
                o = make_float4(x.x * sv, x.y * sv, x.z * sv, x.w * sv);
            } else {
                o = make_float4(0.f, 0.f, 0.f, 0.f);
            }
            dst[v] = o;
        }
        return;
    }

    // ============ COMPUTE WARPS (4 warps, 128 threads) ============
    const int h  = t >> 5;                   // head 0..3 (one warp per head)
    const int n0 = t & 31;                   // rows n0 and n0+32
    const float* g2r0 = g2s + n0 * 36;
    const float* g2r1 = g2s + (n0 + 32) * 36;

    // ---------------- Phase 3: U rows for n0, n0+32 ----------------
    {
        const ulonglong2* P2 = (const ulonglong2*)(g_P + h * 1024);
        #pragma unroll
        for (int row = 0; row < 2; ++row) {
            const float* gr = row ? g2r1 : g2r0;
            int n = row ? (n0 + 32) : n0;
            unsigned long long Ua[16];
            #pragma unroll
            for (int i = 0; i < 16; ++i) Ua[i] = 0ull;
            for (int c = 0; c < 32; ++c) {
                float g = gr[c];
                unsigned long long gp = pack2(g, g);
                const ulonglong2* pr = P2 + c * 8;
                #pragma unroll
                for (int q = 0; q < 8; ++q) {
                    ulonglong2 pv = pr[q];
                    Ua[q * 2]     = ffma2(gp, pv.x, Ua[q * 2]);
                    Ua[q * 2 + 1] = ffma2(gp, pv.y, Ua[q * 2 + 1]);
                }
            }
            ulonglong2* ud = (ulonglong2*)(Us + (h * 64 + n) * 36);
            #pragma unroll
            for (int q = 0; q < 8; ++q)
                ud[q] = make_ulonglong2(Ua[q * 2], Ua[q * 2 + 1]);
        }
    }

    // ---------------- Phase 2: Tr = g2[n] @ M_h for both rows ----------------
    unsigned long long TrA[16], TrB[16];
    #pragma unroll
    for (int i = 0; i < 16; ++i) { TrA[i] = 0ull; TrB[i] = 0ull; }
    {
        const ulonglong2* M2 = (const ulonglong2*)(g_M + h * 1024);
        for (int c = 0; c < 32; ++c) {
            float ga = g2r0[c], gb = g2r1[c];
            unsigned long long gA = pack2(ga, ga), gB = pack2(gb, gb);
            const ulonglong2* mr = M2 + c * 8;
            #pragma unroll
            for (int q = 0; q < 8; ++q) {
                ulonglong2 mv = mr[q];
                TrA[q * 2]     = ffma2(gA, mv.x, TrA[q * 2]);
                TrA[q * 2 + 1] = ffma2(gA, mv.y, TrA[q * 2 + 1]);
                TrB[q * 2]     = ffma2(gB, mv.x, TrB[q * 2]);
                TrB[q * 2 + 1] = ffma2(gB, mv.y, TrB[q * 2 + 1]);
            }
        }
    }

    // ---------------- Phase 4: scores + softmax for rows n0, n0+32 ----------------
    {
        float* arowA = AAs + (h * 64 + n0) * 65;
        float* arowB = arowA + 32 * 65;
        float4 hA = *(const float4*)(h2s + n0 * 4);
        float4 hB = *(const float4*)(h2s + (n0 + 32) * 4);
        float swA = sws[n0], swB = sws[n0 + 32];
        float maxA = -1e30f, maxB = -1e30f;

        for (int m = 0; m < 64; ++m) {
            const ulonglong2* gm = (const ulonglong2*)(g2s + m * 36);
            unsigned long long aA0 = 0ull, aA1 = 0ull, aB0 = 0ull, aB1 = 0ull;
            #pragma unroll
            for (int q = 0; q < 8; ++q) {
                ulonglong2 gv = gm[q];
                aA0 = ffma2(TrA[q * 2],     gv.x, aA0);
                aA1 = ffma2(TrA[q * 2 + 1], gv.y, aA1);
                aB0 = ffma2(TrB[q * 2],     gv.x, aB0);
                aB1 = ffma2(TrB[q * 2 + 1], gv.y, aB1);
            }
            float2 uA0 = unpack2(aA0), uA1 = unpack2(aA1);
            float2 uB0 = unpack2(aB0), uB1 = unpack2(aB1);
            float accA = (uA0.x + uA0.y) + (uA1.x + uA1.y);
            float accB = (uB0.x + uB0.y) + (uB1.x + uB1.y);
            float4 hm = *(const float4*)(h2s + m * 4);
            float swm = sws[m];
            float gateA = hA.x * hm.x + hA.y * hm.y + hA.z * hm.z;
            float gateB = hB.x * hm.x + hB.y * hm.y + hB.z * hm.z;
            float sA = (accA * gateA + 20.f) * (swA * swm) - 20.f;
            float sB = (accB * gateB + 20.f) * (swB * swm) - 20.f;
            arowA[m] = sA; arowB[m] = sB;
            maxA = fmaxf(maxA, sA); maxB = fmaxf(maxB, sB);
        }
        float sumA = 0.f, sumB = 0.f;
        for (int m = 0; m < 64; ++m) {
            float eA = __expf(arowA[m] - maxA);
            float eB = __expf(arowB[m] - maxB);
            arowA[m] = eA; arowB[m] = eB;
            sumA += eA; sumB += eB;
        }
        float invA = msk[n0]      * 0.5773502691896258f / sumA;
        float invB = msk[n0 + 32] * 0.5773502691896258f / sumB;
        for (int m = 0; m < 64; ++m) {
            float4 hm = *(const float4*)(h2s + m * 4);
            float mm = msk[m], swm = sws[m];
            float gateA = hA.x * hm.x + hA.y * hm.y + hA.z * hm.z;
            float gateB = hB.x * hm.x + hB.y * hm.y + hB.z * hm.z;
            arowA[m] = arowA[m] * invA * mm * (swA * swm) * gateA;
            arowB[m] = arowB[m] * invB * mm * (swB * swm) * gateB;
        }
    }

    asm volatile("bar.sync 1, 128;" ::: "memory");

    // ---------------- Phase 6: g2_out (4 rows x 4 cols / thread) + h2_out ----------------
    {
        const int rowg = t >> 3;             // 0..15  -> rows rowg*4 .. +3
        const int jg   = t & 7;              // 0..7   -> cols jg*4 .. +3
        const int r0 = rowg * 4;
        unsigned long long cc[8];
        #pragma unroll
        for (int i = 0; i < 8; ++i) cc[i] = 0ull;
        float hx[4][3];
        #pragma unroll
        for (int ri = 0; ri < 4; ++ri) { hx[ri][0] = hx[ri][1] = hx[ri][2] = 0.f; }
        const float w0 = wev[0], w1 = wev[1], w2 = wev[2], w3 = wev[3];

        for (int m = 0; m < 64; ++m) {
            float a[4][4];
            #pragma unroll
            for (int hh = 0; hh < 4; ++hh)
                #pragma unroll
                for (int ri = 0; ri < 4; ++ri)
                    a[hh][ri] = AAs[(hh * 64 + r0 + ri) * 65 + m];
            #pragma unroll
            for (int hh = 0; hh < 4; ++hh) {
                ulonglong2 up = *(const ulonglong2*)(Us + (hh * 64 + m) * 36 + jg * 4);
                #pragma unroll
                for (int ri = 0; ri < 4; ++ri) {
                    unsigned long long aa = pack2(a[hh][ri], a[hh][ri]);
                    cc[ri * 2]     = ffma2(aa, up.x, cc[ri * 2]);
                    cc[ri * 2 + 1] = ffma2(aa, up.y, cc[ri * 2 + 1]);
                }
            }
            if ((m >> 3) == jg) {            // partition m over jg for h2_out
                float4 hm = *(const float4*)(h2s + m * 4);
                #pragma unroll
                for (int ri = 0; ri < 4; ++ri) {
                    float aw = a[0][ri] * w0 + a[1][ri] * w1 + a[2][ri] * w2 + a[3][ri] * w3;
                    hx[ri][0] += aw * hm.x;
                    hx[ri][1] += aw * hm.y;
                    hx[ri][2] += aw * hm.z;
                }
            }
        }
        // reduce h2_out partials over the 8 jg lanes (xor over low 3 lane bits)
        #pragma unroll
        for (int d = 1; d < 8; d <<= 1)
            #pragma unroll
            for (int ri = 0; ri < 4; ++ri) {
                hx[ri][0] += __shfl_xor_sync(0xffffffffu, hx[ri][0], d);
                hx[ri][1] += __shfl_xor_sync(0xffffffffu, hx[ri][1], d);
                hx[ri][2] += __shfl_xor_sync(0xffffffffu, hx[ri][2], d);
            }
        if (jg == 0) {
            #pragma unroll
            for (int ri = 0; ri < 4; ++ri) {
                float* ho = out_h2 + (size_t)tile * 192 + (r0 + ri) * 3;
                ho[0] = hx[ri][0]; ho[1] = hx[ri][1]; ho[2] = hx[ri][2];
            }
        }
        float4 bi = *(const float4*)(bias + jg * 4);
        #pragma unroll
        for (int ri = 0; ri < 4; ++ri) {
            float2 c0 = unpack2(cc[ri * 2]), c1 = unpack2(cc[ri * 2 + 1]);
            float4 o = make_float4(c0.x + bi.x, c0.y + bi.y, c1.x + bi.z, c1.y + bi.w);
            *(float4*)(out_g2 + ((size_t)tile * 64 + r0 + ri) * 32 + jg * 4) = o;
        }
    }
}

extern "C" void kernel_launch(void* const* d_in, const int* in_sizes, int n_in,
                              void* d_out, int out_size) {
    (void)in_sizes; (void)n_in; (void)out_size;
    const float* g1_ext = (const float*)d_in[0];
    const float* g2     = (const float*)d_in[1];
    const float* h2     = (const float*)d_in[2];
    const float* sw     = (const float*)d_in[3];
    const float* wqk    = (const float*)d_in[4];
    const float* wv     = (const float*)d_in[5];
    const float* whm    = (const float*)d_in[6];
    const float* bhm    = (const float*)d_in[7];
    const float* wev    = (const float*)d_in[8];
    const int* nlist    = (const int*)d_in[9];
    const int* nmask    = (const int*)d_in[10];

    float* out = (float*)d_out;
    float* out_gg1 = out;
    float* out_g2  = out + 67108864ll;
    float* out_h2  = out + 83886080ll;

    size_t smem = SMEM_FLOATS * sizeof(float);   // 114576 B -> 2 CTAs/SM
    cudaFuncSetAttribute(repformer_kernel,
                         cudaFuncAttributeMaxDynamicSharedMemorySize, (int)smem);

    prep_kernel<<<1, 256>>>(wqk, wv, whm);
    repformer_kernel<<<NF * NLOC, 256, smem>>>(
        g1_ext, g2, h2, sw, bhm, wev, nlist, nmask,
        out_gg1, out_g2, out_h2);
}